// round 7
// baseline (speedup 1.0000x reference)
#include <cuda_runtime.h>
#include <math.h>

#define SLOPE 0.2f
#define NB   32
#define TT   1002
#define DD   16
#define EE   32
#define HH   64
#define LEN  1000
#define NN   (NB*LEN)
#define TPB  128
#define STILE 32          // samples per CTA

#define RS_A 36           // activation row stride (floats), 36 = pad of 32, mult of 4
#define RS_W 68           // transposed-weight row stride, mult of 4, odd/32-friendly

// smem layout offsets (floats)
#define OFF_IT   0                        // It  : 33 * RS_A = 1188
#define OFF_W0T  1188                     // W0t : 33 * RS_W = 2244
#define OFF_W1T  3432                     // W1t : 64 * RS_W = 4352
#define OFF_W2T  7784                     // W2t : 64 * RS_W = 4352
#define OFF_A0   12136                    // A0  : 64 * RS_A = 2304
#define OFF_A1   14440
#define OFF_A2   16744
#define OFF_B0   19048
#define OFF_B1   19112
#define OFF_B2   19176
#define OFF_WO   19240
#define OFF_BO   19304
#define SMEM_FLOATS 19308
#define SMEM_BYTES  (SMEM_FLOATS * 4)

// scratch for per-(n,d) log|dJ|
__device__ float g_logscratch[NN * DD];

// acc[k][m] += Wt[j][o0+k] * Ain[j][s0+m], j = 0..nj-1
static __device__ __forceinline__ void gemv_tile(
    const float* __restrict__ Wt, const float* __restrict__ Ain,
    int nj, int o0, int s0, float acc[4][4])
{
    #pragma unroll 4
    for (int j = 0; j < nj; j++) {
        const float4 wv = *reinterpret_cast<const float4*>(&Wt[j * RS_W + o0]);
        const float4 av = *reinterpret_cast<const float4*>(&Ain[j * RS_A + s0]);
        float wk[4] = {wv.x, wv.y, wv.z, wv.w};
        float am[4] = {av.x, av.y, av.z, av.w};
        #pragma unroll
        for (int k = 0; k < 4; k++)
            #pragma unroll
            for (int m = 0; m < 4; m++)
                acc[k][m] += wk[k] * am[m];
    }
}

__global__ __launch_bounds__(TPB, 2)
void mlp_fused_kernel(
    const float* __restrict__ x,   const float* __restrict__ emb,
    const float* __restrict__ W0,  const float* __restrict__ b0,
    const float* __restrict__ W1,  const float* __restrict__ b1,
    const float* __restrict__ W2,  const float* __restrict__ b2,
    const float* __restrict__ Wo,  const float* __restrict__ bo,
    float* __restrict__ out_res)
{
    extern __shared__ float sm[];
    float* It  = sm + OFF_IT;
    float* W0t = sm + OFF_W0T;
    float* W1t = sm + OFF_W1T;
    float* W2t = sm + OFF_W2T;
    float* A0  = sm + OFF_A0;
    float* A1  = sm + OFF_A1;
    float* A2  = sm + OFF_A2;
    float* sb0 = sm + OFF_B0;
    float* sb1 = sm + OFF_B1;
    float* sb2 = sm + OFF_B2;
    float* sWo = sm + OFF_WO;

    const int d   = blockIdx.y;
    const int tid = threadIdx.x;
    const int n0  = blockIdx.x * STILE;

    // ---- stage W0 transposed: W0t[e][h] = W0[d][h][e], e=0..32 ----
    for (int idx = tid; idx < HH * (EE + 1); idx += TPB) {
        int h = idx / (EE + 1), e = idx - h * (EE + 1);
        W0t[e * RS_W + h] = W0[(d * HH + h) * (EE + 1) + e];
    }
    // ---- stage W1, W2 transposed (float4 gmem reads, scalar smem writes) ----
    {
        const float4* w1g = reinterpret_cast<const float4*>(W1 + d * HH * HH);
        const float4* w2g = reinterpret_cast<const float4*>(W2 + d * HH * HH);
        for (int idx = tid; idx < HH * (HH / 4); idx += TPB) {
            int o = idx >> 4, j4 = idx & 15;
            float4 w = w1g[o * 16 + j4];
            W1t[(4*j4+0) * RS_W + o] = w.x;
            W1t[(4*j4+1) * RS_W + o] = w.y;
            W1t[(4*j4+2) * RS_W + o] = w.z;
            W1t[(4*j4+3) * RS_W + o] = w.w;
            w = w2g[o * 16 + j4];
            W2t[(4*j4+0) * RS_W + o] = w.x;
            W2t[(4*j4+1) * RS_W + o] = w.y;
            W2t[(4*j4+2) * RS_W + o] = w.z;
            W2t[(4*j4+3) * RS_W + o] = w.w;
        }
    }
    for (int i = tid; i < HH; i += TPB) {
        sb0[i] = b0[d * HH + i];
        sb1[i] = b1[d * HH + i];
        sb2[i] = b2[d * HH + i];
        sWo[i] = Wo[d * HH + i];
    }
    if (tid == 0) sm[OFF_BO] = bo[d];

    // ---- stage inputs transposed: It[e][s] = emb[row(s)][e]; It[32][s] = x_t ----
    for (int idx = tid; idx < STILE * EE; idx += TPB) {
        int s = idx >> 5, e = idx & 31;
        int n = n0 + s, b = n / LEN, t = n - b * LEN;
        int row = b * TT + t + 2;                 // LAGS = 2
        It[e * RS_A + s] = emb[(size_t)row * EE + e];
    }
    if (tid < STILE) {
        int n = n0 + tid, b = n / LEN, t = n - b * LEN;
        int row = b * TT + t + 2;
        It[EE * RS_A + tid] = x[(size_t)row * DD + d];
    }
    __syncthreads();

    const int o0 = (tid >> 3) * 4;   // output tile base: 0..60
    const int s0 = (tid & 7) * 4;    // sample tile base: 0..28

    float acc[4][4];

    // ================= forward =================
    // layer 0: inputs It (33 rows)
    #pragma unroll
    for (int k = 0; k < 4; k++)
        #pragma unroll
        for (int m = 0; m < 4; m++) acc[k][m] = 0.f;
    gemv_tile(W0t, It, EE + 1, o0, s0, acc);
    #pragma unroll
    for (int k = 0; k < 4; k++) {
        float bb = sb0[o0 + k];
        #pragma unroll
        for (int m = 0; m < 4; m++) {
            float z = acc[k][m] + bb;
            A0[(o0 + k) * RS_A + s0 + m] = (z >= 0.f) ? z : z * SLOPE;
        }
    }
    __syncthreads();

    // layer 1
    #pragma unroll
    for (int k = 0; k < 4; k++)
        #pragma unroll
        for (int m = 0; m < 4; m++) acc[k][m] = 0.f;
    gemv_tile(W1t, A0, HH, o0, s0, acc);
    #pragma unroll
    for (int k = 0; k < 4; k++) {
        float bb = sb1[o0 + k];
        #pragma unroll
        for (int m = 0; m < 4; m++) {
            float z = acc[k][m] + bb;
            A1[(o0 + k) * RS_A + s0 + m] = (z >= 0.f) ? z : z * SLOPE;
        }
    }
    __syncthreads();

    // layer 2
    #pragma unroll
    for (int k = 0; k < 4; k++)
        #pragma unroll
        for (int m = 0; m < 4; m++) acc[k][m] = 0.f;
    gemv_tile(W2t, A1, HH, o0, s0, acc);
    #pragma unroll
    for (int k = 0; k < 4; k++) {
        float bb = sb2[o0 + k];
        #pragma unroll
        for (int m = 0; m < 4; m++) {
            float z = acc[k][m] + bb;
            A2[(o0 + k) * RS_A + s0 + m] = (z >= 0.f) ? z : z * SLOPE;
        }
    }
    __syncthreads();

    // ---- residual head (warp 0) + tangent seed t0 in place on A0 ----
    // gate reconstructible from sign: a = z*g with g>0 => (a>=0) <=> (z>=0)
    if (tid < STILE) {
        float r = sm[OFF_BO];
        #pragma unroll 8
        for (int h = 0; h < HH; h++) r += sWo[h] * A2[h * RS_A + tid];
        int n = n0 + tid;
        out_res[(size_t)n * DD + d] = r;
    }
    for (int idx = tid; idx < HH * STILE; idx += TPB) {
        int o = idx >> 5, s = idx & 31;
        float a = A0[o * RS_A + s];
        float g = (a >= 0.f) ? 1.f : SLOPE;
        A0[o * RS_A + s] = g * W0t[EE * RS_W + o];   // g0 * W0[:, E]
    }
    __syncthreads();

    // t1 = g1 * (W1 @ t0), in place over A1 (gate from old A1 sign)
    #pragma unroll
    for (int k = 0; k < 4; k++)
        #pragma unroll
        for (int m = 0; m < 4; m++) acc[k][m] = 0.f;
    gemv_tile(W1t, A0, HH, o0, s0, acc);
    #pragma unroll
    for (int k = 0; k < 4; k++)
        #pragma unroll
        for (int m = 0; m < 4; m++) {
            float* p = &A1[(o0 + k) * RS_A + s0 + m];
            float g = (*p >= 0.f) ? 1.f : SLOPE;
            *p = g * acc[k][m];
        }
    __syncthreads();

    // t2 = g2 * (W2 @ t1), in place over A2
    #pragma unroll
    for (int k = 0; k < 4; k++)
        #pragma unroll
        for (int m = 0; m < 4; m++) acc[k][m] = 0.f;
    gemv_tile(W2t, A1, HH, o0, s0, acc);
    #pragma unroll
    for (int k = 0; k < 4; k++)
        #pragma unroll
        for (int m = 0; m < 4; m++) {
            float* p = &A2[(o0 + k) * RS_A + s0 + m];
            float g = (*p >= 0.f) ? 1.f : SLOPE;
            *p = g * acc[k][m];
        }
    __syncthreads();

    // ---- Jacobian head ----
    if (tid < STILE) {
        float dJ = 0.f;
        #pragma unroll 8
        for (int h = 0; h < HH; h++) dJ += sWo[h] * A2[h * RS_A + tid];
        int n = n0 + tid;
        g_logscratch[(size_t)n * DD + d] = logf(fabsf(dJ));
    }
}

// deterministic fixed-order reduction over d for log|det J|
__global__ void logdet_reduce_kernel(float* __restrict__ out_log)
{
    int n = blockIdx.x * 256 + threadIdx.x;
    if (n >= NN) return;
    const float4* p = reinterpret_cast<const float4*>(&g_logscratch[(size_t)n * DD]);
    float s = 0.f;
    #pragma unroll
    for (int i = 0; i < DD / 4; i++) {
        float4 v4 = p[i];
        s += v4.x; s += v4.y; s += v4.z; s += v4.w;
    }
    out_log[n] = s;
}

extern "C" void kernel_launch(void* const* d_in, const int* in_sizes, int n_in,
                              void* d_out, int out_size)
{
    const float* x   = (const float*)d_in[0];
    const float* emb = (const float*)d_in[1];
    const float* W0  = (const float*)d_in[2];
    const float* b0  = (const float*)d_in[3];
    const float* W1  = (const float*)d_in[4];
    const float* b1  = (const float*)d_in[5];
    const float* W2  = (const float*)d_in[6];
    const float* b2  = (const float*)d_in[7];
    const float* Wo  = (const float*)d_in[8];
    const float* bo  = (const float*)d_in[9];

    float* out_res = (float*)d_out;            // [N, D]
    float* out_log = (float*)d_out + NN * DD;  // [N]

    cudaFuncSetAttribute(mlp_fused_kernel,
                         cudaFuncAttributeMaxDynamicSharedMemorySize, SMEM_BYTES);

    dim3 grid(NN / STILE, DD);   // 1000 x 16
    mlp_fused_kernel<<<grid, TPB, SMEM_BYTES>>>(x, emb, W0, b0, W1, b1, W2, b2, Wo, bo, out_res);
    logdet_reduce_kernel<<<(NN + 255) / 256, 256>>>(out_log);
}

// round 9
// speedup vs baseline: 1.0331x; 1.0331x over previous
#include <cuda_runtime.h>
#include <math.h>

#define SLOPE 0.2f
#define NB   32
#define TT   1002
#define DD   16
#define EE   32
#define HH   64
#define LEN  1000
#define NN   (NB*LEN)
#define TPB  128
#define STILE 64          // samples per CTA

#define RS_A 68           // activation row stride (floats): 64 + 4 pad, 16B-aligned rows
#define RS_W 68           // transposed-weight row stride

// smem layout offsets (floats)
#define OFF_IT   0                         // It  : 33 * 68 = 2244
#define OFF_W0T  2244                      // W0t : 33 * 68 = 2244
#define OFF_W1T  4488                      // W1t : 64 * 68 = 4352
#define OFF_W2T  8840                      // W2t : 64 * 68 = 4352
#define OFF_A0   13192                     // A0  : 64 * 68 = 4352
#define OFF_A1   17544
#define OFF_A2   21896
#define OFF_B0   26248
#define OFF_B1   26312
#define OFF_B2   26376
#define OFF_WO   26440
#define OFF_BO   26504
#define SMEM_FLOATS 26508
#define SMEM_BYTES  (SMEM_FLOATS * 4)

// scratch for per-(n,d) log|dJ|
__device__ float g_logscratch[NN * DD];

// ---- packed f32x2 helpers (sm_100+) ----
static __device__ __forceinline__ unsigned long long pack2(float v) {
    unsigned long long r;
    unsigned u = __float_as_uint(v);
    asm("mov.b64 %0, {%1, %1};" : "=l"(r) : "r"(u));
    return r;
}
static __device__ __forceinline__ void fma2(unsigned long long& d,
                                            unsigned long long a,
                                            unsigned long long b) {
    asm("fma.rn.f32x2 %0, %1, %2, %0;" : "+l"(d) : "l"(a), "l"(b));
}
static __device__ __forceinline__ void unpack2(unsigned long long v, float& lo, float& hi) {
    unsigned ulo, uhi;
    asm("mov.b64 {%0, %1}, %2;" : "=r"(ulo), "=r"(uhi) : "l"(v));
    lo = __uint_as_float(ulo);
    hi = __uint_as_float(uhi);
}

// acc[k][m] += Wt[j][o0+k] * Ain[j][s0 + 2m .. 2m+1]  (packed pairs), j = 0..nj-1
static __device__ __forceinline__ void gemv_tile_f2(
    const float* __restrict__ Wt, const float* __restrict__ Ain,
    int nj, int o0, int s0, unsigned long long acc[4][4])
{
    #pragma unroll 4
    for (int j = 0; j < nj; j++) {
        const float4 wv = *reinterpret_cast<const float4*>(&Wt[j * RS_W + o0]);
        const ulonglong2 p0 = *reinterpret_cast<const ulonglong2*>(&Ain[j * RS_A + s0]);
        const ulonglong2 p1 = *reinterpret_cast<const ulonglong2*>(&Ain[j * RS_A + s0 + 4]);
        unsigned long long am[4] = {p0.x, p0.y, p1.x, p1.y};
        unsigned long long wk[4] = {pack2(wv.x), pack2(wv.y), pack2(wv.z), pack2(wv.w)};
        #pragma unroll
        for (int k = 0; k < 4; k++)
            #pragma unroll
            for (int m = 0; m < 4; m++)
                fma2(acc[k][m], wk[k], am[m]);
    }
}

static __device__ __forceinline__ void zero_acc(unsigned long long acc[4][4]) {
    #pragma unroll
    for (int k = 0; k < 4; k++)
        #pragma unroll
        for (int m = 0; m < 4; m++) acc[k][m] = 0ull;
}

__global__ __launch_bounds__(TPB, 2)
void mlp_fused_kernel(
    const float* __restrict__ x,   const float* __restrict__ emb,
    const float* __restrict__ W0,  const float* __restrict__ b0,
    const float* __restrict__ W1,  const float* __restrict__ b1,
    const float* __restrict__ W2,  const float* __restrict__ b2,
    const float* __restrict__ Wo,  const float* __restrict__ bo,
    float* __restrict__ out_res)
{
    extern __shared__ float sm[];
    float* It  = sm + OFF_IT;
    float* W0t = sm + OFF_W0T;
    float* W1t = sm + OFF_W1T;
    float* W2t = sm + OFF_W2T;
    float* A0  = sm + OFF_A0;
    float* A1  = sm + OFF_A1;
    float* A2  = sm + OFF_A2;
    float* sb0 = sm + OFF_B0;
    float* sb1 = sm + OFF_B1;
    float* sb2 = sm + OFF_B2;
    float* sWo = sm + OFF_WO;

    const int d   = blockIdx.y;
    const int tid = threadIdx.x;
    const int n0  = blockIdx.x * STILE;

    // ---- stage W0 transposed: W0t[e][h] = W0[d][h][e] ----
    for (int idx = tid; idx < HH * (EE + 1); idx += TPB) {
        int h = idx / (EE + 1), e = idx - h * (EE + 1);
        W0t[e * RS_W + h] = W0[(d * HH + h) * (EE + 1) + e];
    }
    // ---- stage W1, W2 transposed ----
    {
        const float4* w1g = reinterpret_cast<const float4*>(W1 + d * HH * HH);
        const float4* w2g = reinterpret_cast<const float4*>(W2 + d * HH * HH);
        for (int idx = tid; idx < HH * (HH / 4); idx += TPB) {
            int o = idx >> 4, j4 = idx & 15;
            float4 w = w1g[o * 16 + j4];
            W1t[(4*j4+0) * RS_W + o] = w.x;
            W1t[(4*j4+1) * RS_W + o] = w.y;
            W1t[(4*j4+2) * RS_W + o] = w.z;
            W1t[(4*j4+3) * RS_W + o] = w.w;
            w = w2g[o * 16 + j4];
            W2t[(4*j4+0) * RS_W + o] = w.x;
            W2t[(4*j4+1) * RS_W + o] = w.y;
            W2t[(4*j4+2) * RS_W + o] = w.z;
            W2t[(4*j4+3) * RS_W + o] = w.w;
        }
    }
    for (int i = tid; i < HH; i += TPB) {
        sb0[i] = b0[d * HH + i];
        sb1[i] = b1[d * HH + i];
        sb2[i] = b2[d * HH + i];
        sWo[i] = Wo[d * HH + i];
    }
    if (tid == 0) sm[OFF_BO] = bo[d];

    // ---- stage inputs transposed: It[e][s] = emb[row(s)][e]; It[32][s] = x_t ----
    for (int idx = tid; idx < STILE * EE; idx += TPB) {
        int s = idx >> 5, e = idx & 31;
        int n = n0 + s, b = n / LEN, t = n - b * LEN;
        int row = b * TT + t + 2;                 // LAGS = 2
        It[e * RS_A + s] = emb[(size_t)row * EE + e];
    }
    if (tid < STILE) {
        int n = n0 + tid, b = n / LEN, t = n - b * LEN;
        int row = b * TT + t + 2;
        It[EE * RS_A + tid] = x[(size_t)row * DD + d];
    }
    __syncthreads();

    const int o0 = (tid >> 3) * 4;    // 0..60
    const int s0 = (tid & 7) * 8;     // 0..56

    unsigned long long acc[4][4];

    // ================= forward =================
    // layer 0 (33 input rows)
    zero_acc(acc);
    gemv_tile_f2(W0t, It, EE + 1, o0, s0, acc);
    #pragma unroll
    for (int k = 0; k < 4; k++) {
        float bb = sb0[o0 + k];
        #pragma unroll
        for (int m = 0; m < 4; m++) {
            float lo, hi; unpack2(acc[k][m], lo, hi);
            float z0 = lo + bb, z1 = hi + bb;
            A0[(o0 + k) * RS_A + s0 + 2*m + 0] = (z0 >= 0.f) ? z0 : z0 * SLOPE;
            A0[(o0 + k) * RS_A + s0 + 2*m + 1] = (z1 >= 0.f) ? z1 : z1 * SLOPE;
        }
    }
    __syncthreads();

    // layer 1
    zero_acc(acc);
    gemv_tile_f2(W1t, A0, HH, o0, s0, acc);
    #pragma unroll
    for (int k = 0; k < 4; k++) {
        float bb = sb1[o0 + k];
        #pragma unroll
        for (int m = 0; m < 4; m++) {
            float lo, hi; unpack2(acc[k][m], lo, hi);
            float z0 = lo + bb, z1 = hi + bb;
            A1[(o0 + k) * RS_A + s0 + 2*m + 0] = (z0 >= 0.f) ? z0 : z0 * SLOPE;
            A1[(o0 + k) * RS_A + s0 + 2*m + 1] = (z1 >= 0.f) ? z1 : z1 * SLOPE;
        }
    }
    __syncthreads();

    // layer 2
    zero_acc(acc);
    gemv_tile_f2(W2t, A1, HH, o0, s0, acc);
    #pragma unroll
    for (int k = 0; k < 4; k++) {
        float bb = sb2[o0 + k];
        #pragma unroll
        for (int m = 0; m < 4; m++) {
            float lo, hi; unpack2(acc[k][m], lo, hi);
            float z0 = lo + bb, z1 = hi + bb;
            A2[(o0 + k) * RS_A + s0 + 2*m + 0] = (z0 >= 0.f) ? z0 : z0 * SLOPE;
            A2[(o0 + k) * RS_A + s0 + 2*m + 1] = (z1 >= 0.f) ? z1 : z1 * SLOPE;
        }
    }
    __syncthreads();

    // ---- residual head + tangent seed t0 (in place on A0) ----
    // gate reconstructible from sign: a = z*g with g>0 => (a>=0) <=> (z>=0)
    if (tid < STILE) {
        float r = sm[OFF_BO];
        #pragma unroll 8
        for (int h = 0; h < HH; h++) r += sWo[h] * A2[h * RS_A + tid];
        int n = n0 + tid;
        out_res[(size_t)n * DD + d] = r;
    }
    for (int idx = tid; idx < HH * STILE; idx += TPB) {
        int o = idx >> 6, s = idx & 63;
        float a = A0[o * RS_A + s];
        float g = (a >= 0.f) ? 1.f : SLOPE;
        A0[o * RS_A + s] = g * W0t[EE * RS_W + o];   // g0 * W0[:, E]
    }
    __syncthreads();

    // t1 = g1 * (W1 @ t0), in place over A1
    zero_acc(acc);
    gemv_tile_f2(W1t, A0, HH, o0, s0, acc);
    #pragma unroll
    for (int k = 0; k < 4; k++)
        #pragma unroll
        for (int m = 0; m < 4; m++) {
            float lo, hi; unpack2(acc[k][m], lo, hi);
            float* p = &A1[(o0 + k) * RS_A + s0 + 2*m];
            float g0 = (p[0] >= 0.f) ? 1.f : SLOPE;
            float g1 = (p[1] >= 0.f) ? 1.f : SLOPE;
            p[0] = g0 * lo;
            p[1] = g1 * hi;
        }
    __syncthreads();

    // t2 = g2 * (W2 @ t1), in place over A2
    zero_acc(acc);
    gemv_tile_f2(W2t, A1, HH, o0, s0, acc);
    #pragma unroll
    for (int k = 0; k < 4; k++)
        #pragma unroll
        for (int m = 0; m < 4; m++) {
            float lo, hi; unpack2(acc[k][m], lo, hi);
            float* p = &A2[(o0 + k) * RS_A + s0 + 2*m];
            float g0 = (p[0] >= 0.f) ? 1.f : SLOPE;
            float g1 = (p[1] >= 0.f) ? 1.f : SLOPE;
            p[0] = g0 * lo;
            p[1] = g1 * hi;
        }
    __syncthreads();

    // ---- Jacobian head ----
    if (tid < STILE) {
        float dJ = 0.f;
        #pragma unroll 8
        for (int h = 0; h < HH; h++) dJ += sWo[h] * A2[h * RS_A + tid];
        int n = n0 + tid;
        g_logscratch[(size_t)n * DD + d] = logf(fabsf(dJ));
    }
}

// deterministic fixed-order reduction over d for log|det J|
__global__ void logdet_reduce_kernel(float* __restrict__ out_log)
{
    int n = blockIdx.x * 256 + threadIdx.x;
    if (n >= NN) return;
    const float4* p = reinterpret_cast<const float4*>(&g_logscratch[(size_t)n * DD]);
    float s = 0.f;
    #pragma unroll
    for (int i = 0; i < DD / 4; i++) {
        float4 v4 = p[i];
        s += v4.x; s += v4.y; s += v4.z; s += v4.w;
    }
    out_log[n] = s;
}

extern "C" void kernel_launch(void* const* d_in, const int* in_sizes, int n_in,
                              void* d_out, int out_size)
{
    const float* x   = (const float*)d_in[0];
    const float* emb = (const float*)d_in[1];
    const float* W0  = (const float*)d_in[2];
    const float* b0  = (const float*)d_in[3];
    const float* W1  = (const float*)d_in[4];
    const float* b1  = (const float*)d_in[5];
    const float* W2  = (const float*)d_in[6];
    const float* b2  = (const float*)d_in[7];
    const float* Wo  = (const float*)d_in[8];
    const float* bo  = (const float*)d_in[9];

    float* out_res = (float*)d_out;            // [N, D]
    float* out_log = (float*)d_out + NN * DD;  // [N]

    cudaFuncSetAttribute(mlp_fused_kernel,
                         cudaFuncAttributeMaxDynamicSharedMemorySize, SMEM_BYTES);

    dim3 grid(NN / STILE, DD);   // 500 x 16
    mlp_fused_kernel<<<grid, TPB, SMEM_BYTES>>>(x, emb, W0, b0, W1, b1, W2, b2, Wo, bo, out_res);
    logdet_reduce_kernel<<<(NN + 255) / 256, 256>>>(out_log);
}